// round 10
// baseline (speedup 1.0000x reference)
#include <cuda_runtime.h>
#include <cuda_fp16.h>
#include <stdint.h>

// Fixed problem shapes
#define B_CONST     16
#define N_CONST     2048
#define S_CONST     4096
#define D_CONST     128
#define VOCAB_CONST 50257
#define NNZ_CONST   1048576
#define ROWS        (B_CONST * N_CONST)     // 32768 output rows
#define CAP         128                     // bucket capacity (Poisson(32); overflow ~ e^-81)

#define CONV_ELEMS8   ((size_t)VOCAB_CONST * D_CONST / 8)     // 8-float groups
#define PREP_BLOCKS   2048
#define PREP_THREADS  (PREP_BLOCKS * 256)

// Static scratch (__device__ globals; zero-initialized at module load).
// Bucket entry: .x = token id, .y = half2(v, v) bits. Slots >= cnt are never
// written in any replay -> stay zero (padding gathers row 0 with weight 0).
__device__ uint2  g_bucket[(size_t)ROWS * CAP];               // 32 MB
__device__ int    g_cursor[ROWS];
__device__ __half g_htable[(size_t)VOCAB_CONST * D_CONST];    // 12.9 MB fp16 shadow

// ---------------------------------------------------------------------------
// Phase 1 (fused, grid-stride): every block does a slice of BOTH the bucket
// fill and the fp32->fp16 table conversion -> no two-population tail
// imbalance across SMs.
// ---------------------------------------------------------------------------
__global__ __launch_bounds__(256) void prep_kernel(
    const int*   __restrict__ subnode_ids,
    const int*   __restrict__ mask_batch,
    const int*   __restrict__ mask_node,
    const int*   __restrict__ mask_subnode,
    const float* __restrict__ mask_values,
    const float* __restrict__ emb_table)
{
    const int t0 = blockIdx.x * 256 + threadIdx.x;

    // ---- fill slice ----
    for (int i = t0; i < NNZ_CONST; i += PREP_THREADS) {
        const int   b    = __ldg(mask_batch   + i);
        const int   node = __ldg(mask_node    + i);
        const int   sub  = __ldg(mask_subnode + i);
        const float val  = __ldg(mask_values  + i);
        const int   tok  = __ldg(subnode_ids + b * S_CONST + sub);

        const int row = b * N_CONST + node;
        const int pos = atomicAdd(&g_cursor[row], 1);
        if (pos < CAP) {
            const __half  h  = __float2half_rn(val);
            const __half2 h2 = __halves2half2(h, h);
            uint2 e;
            e.x = (unsigned)tok;
            e.y = *reinterpret_cast<const unsigned*>(&h2);
            g_bucket[(size_t)row * CAP + pos] = e;
        }
    }

    // ---- convert slice (8 floats / iteration) ----
    for (size_t j = t0; j < CONV_ELEMS8; j += PREP_THREADS) {
        const float4 f0 = __ldg(reinterpret_cast<const float4*>(emb_table) + 2 * j);
        const float4 f1 = __ldg(reinterpret_cast<const float4*>(emb_table) + 2 * j + 1);
        __half2 h0 = __float22half2_rn(make_float2(f0.x, f0.y));
        __half2 h1 = __float22half2_rn(make_float2(f0.z, f0.w));
        __half2 h2 = __float22half2_rn(make_float2(f1.x, f1.y));
        __half2 h3 = __float22half2_rn(make_float2(f1.z, f1.w));
        uint4 u;
        u.x = *reinterpret_cast<unsigned*>(&h0);
        u.y = *reinterpret_cast<unsigned*>(&h1);
        u.z = *reinterpret_cast<unsigned*>(&h2);
        u.w = *reinterpret_cast<unsigned*>(&h3);
        reinterpret_cast<uint4*>(g_htable)[j] = u;
    }
}

// ---------------------------------------------------------------------------
// Phase 2: ONE warp per row. One entry = one LDG.64 by the full warp
// (32 lanes x 8B = the 256B fp16 row). 4-entry groups double-buffered
// (8 loads in flight); half2 partials flushed to fp32 every 2 groups
// (8 entries) to halve conversion overhead. Block = 128 threads = 4 rows.
// ---------------------------------------------------------------------------
__global__ __launch_bounds__(128, 12) void accumulate_kernel(
    float* __restrict__ out)   // [B*N, D]
{
    const int wib  = threadIdx.x >> 5;      // warp in block: 0..3
    const int row  = blockIdx.x * 4 + wib;
    const int lane = threadIdx.x & 31;      // D-halves [4*lane, 4*lane+4)

    int cnt = g_cursor[row];
    cnt = cnt < CAP ? cnt : CAP;

    const uint2* __restrict__ p = g_bucket + (size_t)row * CAP;
    const __half* __restrict__ tab = g_htable;

    float facc[4];
    #pragma unroll
    for (int q = 0; q < 4; q++) facc[q] = 0.f;

    #define LOADG(BUF, G) do {                                                  \
        _Pragma("unroll")                                                       \
        for (int L = 0; L < 4; L++) {                                           \
            const unsigned tk = __shfl_sync(0xffffffffu, e.x, (G) * 4 + L);     \
            ub[BUF][L] = *reinterpret_cast<const uint2*>(                       \
                tab + (size_t)tk * D_CONST + lane * 4);                         \
        }                                                                       \
    } while (0)

    // Accumulate group G's 4 entries into h0/h1 (no flush here).
    #define CONS(BUF, G) do {                                                   \
        _Pragma("unroll")                                                       \
        for (int L = 0; L < 4; L++) {                                           \
            const unsigned vv = __shfl_sync(0xffffffffu, e.y, (G) * 4 + L);     \
            const __half2 v2 = *reinterpret_cast<const __half2*>(&vv);          \
            const uint2   u  = ub[BUF][L];                                      \
            h0 = __hfma2(v2, *reinterpret_cast<const __half2*>(&u.x), h0);      \
            h1 = __hfma2(v2, *reinterpret_cast<const __half2*>(&u.y), h1);      \
        }                                                                       \
    } while (0)

    for (int base = 0; base < cnt; base += 32) {
        // Unconditional: slots >= cnt are zero (never written in any replay).
        const uint2 e = __ldg(p + base + lane);
        const int rem  = cnt - base;
        const int ngrp = rem < 32 ? ((rem + 3) >> 2) : 8;   // 1..8 groups of 4

        uint2 ub[2][4];
        LOADG(0, 0);
        int g = 0;
        while (true) {
            __half2 h0 = __float2half2_rn(0.f), h1 = h0;
            if (g + 1 < ngrp) LOADG(1, g + 1);
            CONS(0, g);
            g++;
            if (g < ngrp) {
                if (g + 1 < ngrp) LOADG(0, g + 1);
                CONS(1, g);
                g++;
            }
            // Flush 8 entries' worth of half2 partials to fp32
            float2 f;
            f = __half22float2(h0); facc[0] += f.x; facc[1] += f.y;
            f = __half22float2(h1); facc[2] += f.x; facc[3] += f.y;
            if (g >= ngrp) break;
        }
    }
    #undef LOADG
    #undef CONS

    *reinterpret_cast<float4*>(out + (size_t)row * D_CONST + lane * 4) =
        make_float4(facc[0], facc[1], facc[2], facc[3]);
    if (lane == 0) g_cursor[row] = 0;       // reset for next graph replay
}

// ---------------------------------------------------------------------------
// Inputs (metadata order):
//   0: subnode_ids [B*S] i32, 1: mask_batch [NNZ] i32, 2: mask_node [NNZ] i32,
//   3: mask_subnode [NNZ] i32, 4: mask_values [NNZ] f32, 5: emb_table [VOCAB*D] f32
// Output: [B*N*D] f32
// ---------------------------------------------------------------------------
extern "C" void kernel_launch(void* const* d_in, const int* in_sizes, int n_in,
                              void* d_out, int out_size) {
    const int*   subnode_ids  = (const int*)  d_in[0];
    const int*   mask_batch   = (const int*)  d_in[1];
    const int*   mask_node    = (const int*)  d_in[2];
    const int*   mask_subnode = (const int*)  d_in[3];
    const float* mask_values  = (const float*)d_in[4];
    const float* emb_table    = (const float*)d_in[5];
    float*       out          = (float*)d_out;

    prep_kernel<<<PREP_BLOCKS, 256>>>(
        subnode_ids, mask_batch, mask_node, mask_subnode, mask_values, emb_table);

    accumulate_kernel<<<ROWS / 4, 128>>>(out);
}

// round 11
// speedup vs baseline: 1.0056x; 1.0056x over previous
#include <cuda_runtime.h>
#include <cuda_fp16.h>
#include <stdint.h>

// Fixed problem shapes
#define B_CONST     16
#define N_CONST     2048
#define S_CONST     4096
#define D_CONST     128
#define VOCAB_CONST 50257
#define NNZ_CONST   1048576
#define ROWS        (B_CONST * N_CONST)     // 32768 output rows
#define CAP         128                     // bucket capacity (Poisson(32); overflow ~ e^-81)

#define FILL_BLOCKS   (NNZ_CONST / 256)                       // 4096
#define CONV_ELEMS8   ((size_t)VOCAB_CONST * D_CONST / 8)     // 8-float groups
#define CONV_BLOCKS   ((int)((CONV_ELEMS8 + 255) / 256))

// Accumulate: one resident wave, grid-stride over rows.
#define ACC_BLOCKS    1776                  // 148 SMs x 12 blocks
#define ACC_WARPS     (ACC_BLOCKS * 4)      // 7104 warps

// Static scratch (__device__ globals; zero-initialized at module load).
// Bucket entry: .x = BYTE OFFSET of the token's fp16 row (tok*256),
//               .y = half2(v, v) bits. Slots >= cnt never written -> zero.
__device__ uint2  g_bucket[(size_t)ROWS * CAP];               // 32 MB
__device__ int    g_cursor[ROWS];
__device__ __half g_htable[(size_t)VOCAB_CONST * D_CONST];    // 12.9 MB fp16 shadow

// ---------------------------------------------------------------------------
// Phase 1 (fused, split block populations -> fill and convert run
// CONCURRENTLY across SMs): blocks [0, FILL_BLOCKS) bucket nnz entries;
// remaining blocks convert emb_table fp32 -> fp16 (8 floats/thread).
// ---------------------------------------------------------------------------
__global__ __launch_bounds__(256) void prep_kernel(
    const int*   __restrict__ subnode_ids,
    const int*   __restrict__ mask_batch,
    const int*   __restrict__ mask_node,
    const int*   __restrict__ mask_subnode,
    const float* __restrict__ mask_values,
    const float* __restrict__ emb_table)
{
    const int blk = blockIdx.x;
    if (blk < FILL_BLOCKS) {
        const int i = blk * 256 + threadIdx.x;
        const int   b    = __ldg(mask_batch   + i);
        const int   node = __ldg(mask_node    + i);
        const int   sub  = __ldg(mask_subnode + i);
        const float val  = __ldg(mask_values  + i);
        const int   tok  = __ldg(subnode_ids + b * S_CONST + sub);

        const int row = b * N_CONST + node;
        const int pos = atomicAdd(&g_cursor[row], 1);
        if (pos < CAP) {
            const __half  h  = __float2half_rn(val);
            const __half2 h2 = __halves2half2(h, h);
            uint2 e;
            e.x = (unsigned)tok * (D_CONST * 2);   // byte offset of fp16 row
            e.y = *reinterpret_cast<const unsigned*>(&h2);
            g_bucket[(size_t)row * CAP + pos] = e;
        }
    } else {
        const size_t j = (size_t)(blk - FILL_BLOCKS) * 256 + threadIdx.x;
        if (j < CONV_ELEMS8) {
            const float4 f0 = __ldg(reinterpret_cast<const float4*>(emb_table) + 2 * j);
            const float4 f1 = __ldg(reinterpret_cast<const float4*>(emb_table) + 2 * j + 1);
            __half2 h0 = __float22half2_rn(make_float2(f0.x, f0.y));
            __half2 h1 = __float22half2_rn(make_float2(f0.z, f0.w));
            __half2 h2 = __float22half2_rn(make_float2(f1.x, f1.y));
            __half2 h3 = __float22half2_rn(make_float2(f1.z, f1.w));
            uint4 u;
            u.x = *reinterpret_cast<unsigned*>(&h0);
            u.y = *reinterpret_cast<unsigned*>(&h1);
            u.z = *reinterpret_cast<unsigned*>(&h2);
            u.w = *reinterpret_cast<unsigned*>(&h3);
            reinterpret_cast<uint4*>(g_htable)[j] = u;
        }
    }
}

// ---------------------------------------------------------------------------
// Phase 2 (persistent, one wave): ONE warp per row, warps grid-stride over
// rows. One entry = one LDG.64 by the full warp (32 lanes x 8B = 256B fp16
// row); bucket holds precomputed byte offsets (32-bit add, no IMAD.WIDE).
// 4-entry groups double-buffered (8 loads in flight); flush to fp32 per
// group. Block = 128 threads, 12 blocks/SM.
// ---------------------------------------------------------------------------
__global__ __launch_bounds__(128, 12) void accumulate_kernel(
    float* __restrict__ out)   // [B*N, D]
{
    const int warp0 = blockIdx.x * 4 + (threadIdx.x >> 5);
    const int lane  = threadIdx.x & 31;     // D-halves [4*lane, 4*lane+4)
    const char* __restrict__ tabb =
        reinterpret_cast<const char*>(g_htable) + lane * 8;

    for (int row = warp0; row < ROWS; row += ACC_WARPS) {
        int cnt = g_cursor[row];
        cnt = cnt < CAP ? cnt : CAP;
        const uint2* __restrict__ p = g_bucket + (size_t)row * CAP;

        float facc[4];
        #pragma unroll
        for (int q = 0; q < 4; q++) facc[q] = 0.f;

        #define LOADG(BUF, G) do {                                              \
            _Pragma("unroll")                                                   \
            for (int L = 0; L < 4; L++) {                                       \
                const unsigned off = __shfl_sync(0xffffffffu, e.x, (G)*4 + L);  \
                ub[BUF][L] = *reinterpret_cast<const uint2*>(tabb + off);       \
            }                                                                   \
        } while (0)

        #define CONSUME(BUF, G) do {                                            \
            __half2 h0 = __float2half2_rn(0.f), h1 = h0;                        \
            _Pragma("unroll")                                                   \
            for (int L = 0; L < 4; L++) {                                       \
                const unsigned vv = __shfl_sync(0xffffffffu, e.y, (G)*4 + L);   \
                const __half2 v2 = *reinterpret_cast<const __half2*>(&vv);      \
                const uint2   u  = ub[BUF][L];                                  \
                h0 = __hfma2(v2, *reinterpret_cast<const __half2*>(&u.x), h0);  \
                h1 = __hfma2(v2, *reinterpret_cast<const __half2*>(&u.y), h1);  \
            }                                                                   \
            float2 f;                                                           \
            f = __half22float2(h0); facc[0] += f.x; facc[1] += f.y;             \
            f = __half22float2(h1); facc[2] += f.x; facc[3] += f.y;             \
        } while (0)

        for (int base = 0; base < cnt; base += 32) {
            // Unconditional: slots >= cnt are zero (never written, any replay).
            const uint2 e = __ldg(p + base + lane);
            const int rem  = cnt - base;
            const int ngrp = rem < 32 ? ((rem + 3) >> 2) : 8;   // groups of 4

            uint2 ub[2][4];
            LOADG(0, 0);
            int g = 0;
            while (true) {
                if (g + 1 < ngrp) LOADG(1, g + 1);
                CONSUME(0, g);
                g++;
                if (g >= ngrp) break;
                if (g + 1 < ngrp) LOADG(0, g + 1);
                CONSUME(1, g);
                g++;
                if (g >= ngrp) break;
            }
        }
        #undef LOADG
        #undef CONSUME

        *reinterpret_cast<float4*>(out + (size_t)row * D_CONST + lane * 4) =
            make_float4(facc[0], facc[1], facc[2], facc[3]);
        if (lane == 0) g_cursor[row] = 0;   // reset for next graph replay
    }
}

// ---------------------------------------------------------------------------
// Inputs (metadata order):
//   0: subnode_ids [B*S] i32, 1: mask_batch [NNZ] i32, 2: mask_node [NNZ] i32,
//   3: mask_subnode [NNZ] i32, 4: mask_values [NNZ] f32, 5: emb_table [VOCAB*D] f32
// Output: [B*N*D] f32
// ---------------------------------------------------------------------------
extern "C" void kernel_launch(void* const* d_in, const int* in_sizes, int n_in,
                              void* d_out, int out_size) {
    const int*   subnode_ids  = (const int*)  d_in[0];
    const int*   mask_batch   = (const int*)  d_in[1];
    const int*   mask_node    = (const int*)  d_in[2];
    const int*   mask_subnode = (const int*)  d_in[3];
    const float* mask_values  = (const float*)d_in[4];
    const float* emb_table    = (const float*)d_in[5];
    float*       out          = (float*)d_out;

    prep_kernel<<<FILL_BLOCKS + CONV_BLOCKS, 256>>>(
        subnode_ids, mask_batch, mask_node, mask_subnode, mask_values, emb_table);

    accumulate_kernel<<<ACC_BLOCKS, 128>>>(out);
}